// round 13
// baseline (speedup 1.0000x reference)
#include <cuda_runtime.h>

// Problem constants
#define KCODES   512
#define DIM      64
#define HW       4096      // 64*64
#define NBATCH   32
#define PIXB     256       // pixels per block
#define THREADS  512       // 16 warps -> 4 per SMSP (latency hiding)
#define NBLK     512       // (NBATCH*HW)/PIXB
#define TILES_PER_IMG 16   // HW/PIXB
#define ES_STRIDE 68       // padded row stride (floats) for codebook in smem
#define XS_STRIDE 68       // padded row stride (floats) for pixel tile in smem
#define TAU      2e-3f     // fp32 top-2 margin below which we refine in fp64

// device scratch (static allocation — allowed)
__device__ double       g_part[NBLK];
__device__ unsigned int g_done = 0;   // self-resetting via atomicInc wraparound

// packed dual-FP32 FMA: acc.{lo,hi} += a.{lo,hi} * b.{lo,hi}
__device__ __forceinline__ void ffma2(unsigned long long &acc,
                                      unsigned long long a,
                                      unsigned long long b) {
    asm("fma.rn.f32x2 %0, %1, %2, %0;" : "+l"(acc) : "l"(a), "l"(b));
}

__global__ __launch_bounds__(THREADS, 1)
void vq_main(const float* __restrict__ feat,
             const float* __restrict__ emb,
             float* __restrict__ out, int last) {
    extern __shared__ float sm[];
    float* es    = sm;                               // [512][68]
    float* xs    = es + KCODES * ES_STRIDE;          // [256][68]
    float* e2s   = xs + PIXB * XS_STRIDE;            // [512]
    int*   bestk = (int*)(e2s + KCODES);             // [256]
    float* wsum  = (float*)(bestk + PIXB);           // [16]
    int*   nflag = (int*)(wsum + 16);                // [1]
    int*   flags = nflag + 1;                        // [256]

    __shared__ int    s_last;
    __shared__ double s_red[THREADS];

    const int t   = threadIdx.x;
    const int bid = blockIdx.x;
    const int b   = bid >> 4;                         // 16 tiles per image
    const int p0  = (bid & (TILES_PER_IMG - 1)) * PIXB;
    const float* fbase = feat + ((size_t)b * DIM) * HW + p0;

    if (t == 0) *nflag = 0;

    // ---- stage codebook into smem (natural [k][d], padded rows, float4) ----
    {
        const float4* g4 = (const float4*)emb;
        for (int i = t; i < KCODES * (DIM / 4); i += THREADS) {
            int k  = i >> 4;
            int d4 = i & 15;
            *(float4*)&es[k * ES_STRIDE + d4 * 4] = g4[i];
        }
    }
    // ---- stage 256-pixel tile, transposing NCHW [d][p] -> xs[p][d] ----
    for (int i = t; i < PIXB * DIM; i += THREADS) {
        int d = i >> 8;
        int p = i & (PIXB - 1);
        xs[p * XS_STRIDE + d] = fbase[(size_t)d * HW + p];
    }
    __syncthreads();

    // ---- per-code squared norms ----
    for (int k = t; k < KCODES; k += THREADS) {
        const float* er = &es[k * ES_STRIDE];
        float s = 0.f;
        #pragma unroll
        for (int d = 0; d < DIM; d++) s = fmaf(er[d], er[d], s);
        e2s[k] = s;
    }
    __syncthreads();

    // ---- GEMM-style distance + top-2 argmin ----
    // thread tile: 4 pixels x 8 codes.
    //   pixels: pg + j*64   (j = 0..3)  -> x LDS conflict-free (row stride 1 in pg)
    //   codes:  kc*64 + jj*8 + kg       -> ev LDS conflict-free (row stride 1 in kg)
    const int pg = t >> 3;   // 0..63
    const int kg = t & 7;    // 0..7

    float s1[4], s2[4];
    int   i1[4];
    #pragma unroll
    for (int j = 0; j < 4; j++) { s1[j] = 3.4e38f; s2[j] = 3.4e38f; i1[j] = 0; }

    const float* xbase = &xs[pg * XS_STRIDE];

    for (int kc = 0; kc < 8; kc++) {
        const int kbase = kc * 64 + kg;
        const float* erow = &es[kbase * ES_STRIDE];

        unsigned long long acc[4][8];
        #pragma unroll
        for (int j = 0; j < 4; j++)
            #pragma unroll
            for (int jj = 0; jj < 8; jj++) acc[j][jj] = 0ULL;

        // unroll 1: keep live register set under the 128-reg cap (no spills)
        #pragma unroll 1
        for (int d4 = 0; d4 < 16; d4++) {
            ulonglong2 xv0 = *(const ulonglong2*)&xbase[0 * 64 * XS_STRIDE + d4 * 4];
            ulonglong2 xv1 = *(const ulonglong2*)&xbase[1 * 64 * XS_STRIDE + d4 * 4];
            ulonglong2 xv2 = *(const ulonglong2*)&xbase[2 * 64 * XS_STRIDE + d4 * 4];
            ulonglong2 xv3 = *(const ulonglong2*)&xbase[3 * 64 * XS_STRIDE + d4 * 4];
            #pragma unroll
            for (int jj = 0; jj < 8; jj++) {
                ulonglong2 ev =
                    *(const ulonglong2*)&erow[jj * 8 * ES_STRIDE + d4 * 4];
                // interleaved: 4 independent accs between reuses (no RAW stall)
                ffma2(acc[0][jj], xv0.x, ev.x);
                ffma2(acc[1][jj], xv1.x, ev.x);
                ffma2(acc[2][jj], xv2.x, ev.x);
                ffma2(acc[3][jj], xv3.x, ev.x);
                ffma2(acc[0][jj], xv0.y, ev.y);
                ffma2(acc[1][jj], xv1.y, ev.y);
                ffma2(acc[2][jj], xv2.y, ev.y);
                ffma2(acc[3][jj], xv3.y, ev.y);
            }
        }

        // epilogue: score = e2 - 2*dot ; top-2 (strict <, ascending code order)
        #pragma unroll
        for (int jj = 0; jj < 8; jj++) {
            const int code = kbase + jj * 8;
            const float e2v = e2s[code];
            #pragma unroll
            for (int j = 0; j < 4; j++) {
                unsigned long long a = acc[j][jj];
                float lo = __uint_as_float((unsigned)a);
                float hi = __uint_as_float((unsigned)(a >> 32));
                float dot = lo + hi;
                float score = fmaf(-2.f, dot, e2v);
                if (score < s1[j]) { s2[j] = s1[j]; s1[j] = score; i1[j] = code; }
                else if (score < s2[j]) { s2[j] = score; }
            }
        }
    }

    // ---- reduce top-2 across the 8 kg-lanes (same pg), tie -> smaller index ----
    #pragma unroll
    for (int j = 0; j < 4; j++) {
        float a1 = s1[j], a2 = s2[j];
        int   ai = i1[j];
        #pragma unroll
        for (int off = 1; off < 8; off <<= 1) {
            float o1 = __shfl_xor_sync(0xffffffffu, a1, off);
            int   oi = __shfl_xor_sync(0xffffffffu, ai, off);
            float o2 = __shfl_xor_sync(0xffffffffu, a2, off);
            if (o1 < a1 || (o1 == a1 && oi < ai)) {
                a2 = fminf(a1, o2); a1 = o1; ai = oi;
            } else {
                a2 = fminf(a2, o1);
            }
        }
        if (kg == 0) {
            const int p = j * 64 + pg;
            bestk[p] = ai;
            if (a2 - a1 < TAU) {
                int slot = atomicAdd(nflag, 1);
                flags[slot] = p;
            }
        }
    }
    __syncthreads();

    // ---- fp64 exact refinement of near-tie pixels (one warp per pixel) ----
    {
        const int nf   = *nflag;
        const int wid  = t >> 5;   // 16 warps
        const int lane = t & 31;
        for (int f = wid; f < nf; f += 16) {
            const int p = flags[f];
            const float* xr = &xs[p * XS_STRIDE];
            double bs = 1e300;
            int    bi = 0x7fffffff;
            for (int k = lane; k < KCODES; k += 32) {
                const float* er = &es[k * ES_STRIDE];
                double a0 = 0.0, a1d = 0.0, a2d = 0.0, a3d = 0.0;
                #pragma unroll
                for (int d = 0; d < DIM; d += 4) {
                    double d0 = (double)xr[d + 0] - (double)er[d + 0];
                    double d1 = (double)xr[d + 1] - (double)er[d + 1];
                    double d2 = (double)xr[d + 2] - (double)er[d + 2];
                    double d3 = (double)xr[d + 3] - (double)er[d + 3];
                    a0  = fma(d0, d0, a0);
                    a1d = fma(d1, d1, a1d);
                    a2d = fma(d2, d2, a2d);
                    a3d = fma(d3, d3, a3d);
                }
                double s = (a0 + a1d) + (a2d + a3d);
                if (s < bs) { bs = s; bi = k; }   // ascending k -> first occurrence
            }
            #pragma unroll
            for (int off = 16; off > 0; off >>= 1) {
                double os = __shfl_xor_sync(0xffffffffu, bs, off);
                int    oi = __shfl_xor_sync(0xffffffffu, bi, off);
                if (os < bs || (os == bs && oi < bi)) { bs = os; bi = oi; }
            }
            if (lane == 0) bestk[p] = bi;
        }
    }
    __syncthreads();

    // ---- gather output (NCHW) + elementwise-exact loss partial ----
    float lsum = 0.f;
    float* outb = out + ((size_t)b * DIM) * HW + p0;
    for (int i = t; i < PIXB * DIM; i += THREADS) {
        int d = i >> 8;
        int p = i & (PIXB - 1);
        int k = bestk[p];
        float ev = es[k * ES_STRIDE + d];
        float xv = xs[p * XS_STRIDE + d];
        outb[(size_t)d * HW + p] = ev;     // st == quant_out (forward value)
        float df = ev - xv;
        lsum = fmaf(df, df, lsum);
    }
    #pragma unroll
    for (int off = 16; off > 0; off >>= 1)
        lsum += __shfl_xor_sync(0xffffffffu, lsum, off);
    if ((t & 31) == 0) wsum[t >> 5] = lsum;
    __syncthreads();

    // ---- fused loss finalization: last block reduces all partials ----
    if (t == 0) {
        double s = 0.0;
        #pragma unroll
        for (int w = 0; w < 16; w++) s += (double)wsum[w];
        g_part[bid] = s;
        __threadfence();
        unsigned int old = atomicInc(&g_done, NBLK - 1);  // wraps to 0 => reset
        s_last = (old == NBLK - 1);
    }
    __syncthreads();

    if (s_last) {
        // deterministic fixed-order reduction of 512 partials
        s_red[t] = g_part[t];
        __syncthreads();
        #pragma unroll
        for (int sred = THREADS / 2; sred > 0; sred >>= 1) {
            if (t < sred) s_red[t] += s_red[t + sred];
            __syncthreads();
        }
        if (t == 0) {
            // loss = commitment + beta*codebook = 1.2 * mean(min dist^2)
            out[last] = (float)(1.2 * s_red[0]
                                / (double)(NBATCH * DIM * HW));
        }
    }
}

extern "C" void kernel_launch(void* const* d_in, const int* in_sizes, int n_in,
                              void* d_out, int out_size) {
    const float* feat = (const float*)d_in[0];   // (32, 64, 64, 64) fp32 NCHW
    const float* emb  = (const float*)d_in[1];   // (512, 64) fp32
    float* out = (float*)d_out;                  // st (8388608 floats) + loss (1)

    const int smem_bytes =
        (KCODES * ES_STRIDE + PIXB * XS_STRIDE + KCODES) * (int)sizeof(float)
        + PIXB * (int)sizeof(int)
        + 16 * (int)sizeof(float)
        + (1 + PIXB) * (int)sizeof(int);

    cudaFuncSetAttribute(vq_main, cudaFuncAttributeMaxDynamicSharedMemorySize,
                         smem_bytes);

    vq_main<<<NBLK, THREADS, smem_bytes>>>(feat, emb, out, out_size - 1);
}

// round 14
// speedup vs baseline: 1.0001x; 1.0001x over previous
#include <cuda_runtime.h>

// Problem constants
#define KCODES   512
#define DIM      64
#define HW       4096      // 64*64
#define NBATCH   32
#define PIXB     256       // pixels per block
#define THREADS  512       // 16 warps -> 4 per SMSP (latency hiding)
#define NBLK     512       // (NBATCH*HW)/PIXB
#define TILES_PER_IMG 16   // HW/PIXB
#define ES_STRIDE 68       // padded row stride (floats) for codebook in smem
#define XS_STRIDE 68       // padded row stride (floats) for pixel tile in smem
#define TAU      2e-3f     // fp32 top-2 margin below which we refine in fp64

// device scratch (static allocation — allowed)
__device__ double       g_part[NBLK];
__device__ unsigned int g_done = 0;   // self-resetting via atomicInc wraparound

// packed dual-FP32 FMA: acc.{lo,hi} += a.{lo,hi} * b.{lo,hi}
__device__ __forceinline__ void ffma2(unsigned long long &acc,
                                      unsigned long long a,
                                      unsigned long long b) {
    asm("fma.rn.f32x2 %0, %1, %2, %0;" : "+l"(acc) : "l"(a), "l"(b));
}

__global__ __launch_bounds__(THREADS, 1)
void vq_main(const float* __restrict__ feat,
             const float* __restrict__ emb,
             float* __restrict__ out, int last) {
    extern __shared__ float sm[];
    float* es    = sm;                               // [512][68]
    float* xs    = es + KCODES * ES_STRIDE;          // [256][68]
    float* e2s   = xs + PIXB * XS_STRIDE;            // [512]
    int*   bestk = (int*)(e2s + KCODES);             // [256]
    float* wsum  = (float*)(bestk + PIXB);           // [16]
    int*   nflag = (int*)(wsum + 16);                // [1]
    int*   flags = nflag + 1;                        // [256]

    __shared__ int    s_last;
    __shared__ double s_red[THREADS];

    const int t   = threadIdx.x;
    const int bid = blockIdx.x;
    const int b   = bid >> 4;                         // 16 tiles per image
    const int p0  = (bid & (TILES_PER_IMG - 1)) * PIXB;
    const float* fbase = feat + ((size_t)b * DIM) * HW + p0;

    if (t == 0) *nflag = 0;

    // ---- stage codebook into smem (natural [k][d], padded rows, float4) ----
    {
        const float4* g4 = (const float4*)emb;
        for (int i = t; i < KCODES * (DIM / 4); i += THREADS) {
            int k  = i >> 4;
            int d4 = i & 15;
            *(float4*)&es[k * ES_STRIDE + d4 * 4] = g4[i];
        }
    }
    // ---- stage 256-pixel tile, transposing NCHW [d][p] -> xs[p][d] ----
    for (int i = t; i < PIXB * DIM; i += THREADS) {
        int d = i >> 8;
        int p = i & (PIXB - 1);
        xs[p * XS_STRIDE + d] = fbase[(size_t)d * HW + p];
    }
    __syncthreads();

    // ---- per-code squared norms ----
    for (int k = t; k < KCODES; k += THREADS) {
        const float* er = &es[k * ES_STRIDE];
        float s = 0.f;
        #pragma unroll
        for (int d = 0; d < DIM; d++) s = fmaf(er[d], er[d], s);
        e2s[k] = s;
    }
    __syncthreads();

    // ---- GEMM-style distance + top-2 argmin ----
    // thread tile: 4 pixels x 8 codes.
    //   pixels: pg + j*64   (j = 0..3)  -> x LDS conflict-free (row stride 1 in pg)
    //   codes:  kc*64 + jj*8 + kg       -> ev LDS conflict-free (row stride 1 in kg)
    const int pg = t >> 3;   // 0..63
    const int kg = t & 7;    // 0..7

    float s1[4], s2[4];
    int   i1[4];
    #pragma unroll
    for (int j = 0; j < 4; j++) { s1[j] = 3.4e38f; s2[j] = 3.4e38f; i1[j] = 0; }

    const float* xbase = &xs[pg * XS_STRIDE];

    for (int kc = 0; kc < 8; kc++) {
        const int kbase = kc * 64 + kg;
        const float* erow = &es[kbase * ES_STRIDE];

        unsigned long long acc[4][8];
        #pragma unroll
        for (int j = 0; j < 4; j++)
            #pragma unroll
            for (int jj = 0; jj < 8; jj++) acc[j][jj] = 0ULL;

        // unroll 1: keep live register set under the 128-reg cap (no spills)
        #pragma unroll 1
        for (int d4 = 0; d4 < 16; d4++) {
            ulonglong2 xv0 = *(const ulonglong2*)&xbase[0 * 64 * XS_STRIDE + d4 * 4];
            ulonglong2 xv1 = *(const ulonglong2*)&xbase[1 * 64 * XS_STRIDE + d4 * 4];
            ulonglong2 xv2 = *(const ulonglong2*)&xbase[2 * 64 * XS_STRIDE + d4 * 4];
            ulonglong2 xv3 = *(const ulonglong2*)&xbase[3 * 64 * XS_STRIDE + d4 * 4];
            #pragma unroll
            for (int jj = 0; jj < 8; jj++) {
                ulonglong2 ev =
                    *(const ulonglong2*)&erow[jj * 8 * ES_STRIDE + d4 * 4];
                // interleaved: 4 independent accs between reuses (no RAW stall)
                ffma2(acc[0][jj], xv0.x, ev.x);
                ffma2(acc[1][jj], xv1.x, ev.x);
                ffma2(acc[2][jj], xv2.x, ev.x);
                ffma2(acc[3][jj], xv3.x, ev.x);
                ffma2(acc[0][jj], xv0.y, ev.y);
                ffma2(acc[1][jj], xv1.y, ev.y);
                ffma2(acc[2][jj], xv2.y, ev.y);
                ffma2(acc[3][jj], xv3.y, ev.y);
            }
        }

        // epilogue: score = e2 - 2*dot ; top-2 (strict <, ascending code order)
        #pragma unroll
        for (int jj = 0; jj < 8; jj++) {
            const int code = kbase + jj * 8;
            const float e2v = e2s[code];
            #pragma unroll
            for (int j = 0; j < 4; j++) {
                unsigned long long a = acc[j][jj];
                float lo = __uint_as_float((unsigned)a);
                float hi = __uint_as_float((unsigned)(a >> 32));
                float dot = lo + hi;
                float score = fmaf(-2.f, dot, e2v);
                if (score < s1[j]) { s2[j] = s1[j]; s1[j] = score; i1[j] = code; }
                else if (score < s2[j]) { s2[j] = score; }
            }
        }
    }

    // ---- reduce top-2 across the 8 kg-lanes (same pg), tie -> smaller index ----
    #pragma unroll
    for (int j = 0; j < 4; j++) {
        float a1 = s1[j], a2 = s2[j];
        int   ai = i1[j];
        #pragma unroll
        for (int off = 1; off < 8; off <<= 1) {
            float o1 = __shfl_xor_sync(0xffffffffu, a1, off);
            int   oi = __shfl_xor_sync(0xffffffffu, ai, off);
            float o2 = __shfl_xor_sync(0xffffffffu, a2, off);
            if (o1 < a1 || (o1 == a1 && oi < ai)) {
                a2 = fminf(a1, o2); a1 = o1; ai = oi;
            } else {
                a2 = fminf(a2, o1);
            }
        }
        if (kg == 0) {
            const int p = j * 64 + pg;
            bestk[p] = ai;
            if (a2 - a1 < TAU) {
                int slot = atomicAdd(nflag, 1);
                flags[slot] = p;
            }
        }
    }
    __syncthreads();

    // ---- fp64 exact refinement of near-tie pixels (one warp per pixel) ----
    {
        const int nf   = *nflag;
        const int wid  = t >> 5;   // 16 warps
        const int lane = t & 31;
        for (int f = wid; f < nf; f += 16) {
            const int p = flags[f];
            const float* xr = &xs[p * XS_STRIDE];
            double bs = 1e300;
            int    bi = 0x7fffffff;
            for (int k = lane; k < KCODES; k += 32) {
                const float* er = &es[k * ES_STRIDE];
                double a0 = 0.0, a1d = 0.0, a2d = 0.0, a3d = 0.0;
                #pragma unroll
                for (int d = 0; d < DIM; d += 4) {
                    double d0 = (double)xr[d + 0] - (double)er[d + 0];
                    double d1 = (double)xr[d + 1] - (double)er[d + 1];
                    double d2 = (double)xr[d + 2] - (double)er[d + 2];
                    double d3 = (double)xr[d + 3] - (double)er[d + 3];
                    a0  = fma(d0, d0, a0);
                    a1d = fma(d1, d1, a1d);
                    a2d = fma(d2, d2, a2d);
                    a3d = fma(d3, d3, a3d);
                }
                double s = (a0 + a1d) + (a2d + a3d);
                if (s < bs) { bs = s; bi = k; }   // ascending k -> first occurrence
            }
            #pragma unroll
            for (int off = 16; off > 0; off >>= 1) {
                double os = __shfl_xor_sync(0xffffffffu, bs, off);
                int    oi = __shfl_xor_sync(0xffffffffu, bi, off);
                if (os < bs || (os == bs && oi < bi)) { bs = os; bi = oi; }
            }
            if (lane == 0) bestk[p] = bi;
        }
    }
    __syncthreads();

    // ---- gather output (NCHW) + elementwise-exact loss partial ----
    float lsum = 0.f;
    float* outb = out + ((size_t)b * DIM) * HW + p0;
    for (int i = t; i < PIXB * DIM; i += THREADS) {
        int d = i >> 8;
        int p = i & (PIXB - 1);
        int k = bestk[p];
        float ev = es[k * ES_STRIDE + d];
        float xv = xs[p * XS_STRIDE + d];
        outb[(size_t)d * HW + p] = ev;     // st == quant_out (forward value)
        float df = ev - xv;
        lsum = fmaf(df, df, lsum);
    }
    #pragma unroll
    for (int off = 16; off > 0; off >>= 1)
        lsum += __shfl_xor_sync(0xffffffffu, lsum, off);
    if ((t & 31) == 0) wsum[t >> 5] = lsum;
    __syncthreads();

    // ---- fused loss finalization: last block reduces all partials ----
    if (t == 0) {
        double s = 0.0;
        #pragma unroll
        for (int w = 0; w < 16; w++) s += (double)wsum[w];
        g_part[bid] = s;
        __threadfence();
        unsigned int old = atomicInc(&g_done, NBLK - 1);  // wraps to 0 => reset
        s_last = (old == NBLK - 1);
    }
    __syncthreads();

    if (s_last) {
        // deterministic fixed-order reduction of 512 partials
        s_red[t] = g_part[t];
        __syncthreads();
        #pragma unroll
        for (int sred = THREADS / 2; sred > 0; sred >>= 1) {
            if (t < sred) s_red[t] += s_red[t + sred];
            __syncthreads();
        }
        if (t == 0) {
            // loss = commitment + beta*codebook = 1.2 * mean(min dist^2)
            out[last] = (float)(1.2 * s_red[0]
                                / (double)(NBATCH * DIM * HW));
        }
    }
}

extern "C" void kernel_launch(void* const* d_in, const int* in_sizes, int n_in,
                              void* d_out, int out_size) {
    const float* feat = (const float*)d_in[0];   // (32, 64, 64, 64) fp32 NCHW
    const float* emb  = (const float*)d_in[1];   // (512, 64) fp32
    float* out = (float*)d_out;                  // st (8388608 floats) + loss (1)

    const int smem_bytes =
        (KCODES * ES_STRIDE + PIXB * XS_STRIDE + KCODES) * (int)sizeof(float)
        + PIXB * (int)sizeof(int)
        + 16 * (int)sizeof(float)
        + (1 + PIXB) * (int)sizeof(int);

    cudaFuncSetAttribute(vq_main, cudaFuncAttributeMaxDynamicSharedMemorySize,
                         smem_bytes);

    vq_main<<<NBLK, THREADS, smem_bytes>>>(feat, emb, out, out_size - 1);
}

// round 15
// speedup vs baseline: 1.0010x; 1.0010x over previous
#include <cuda_runtime.h>

// Problem constants
#define KCODES   512
#define DIM      64
#define HW       4096      // 64*64
#define NBATCH   32
#define PIXB     256       // pixels per block
#define THREADS  512       // 16 warps -> 4 per SMSP (latency hiding)
#define NBLK     512       // (NBATCH*HW)/PIXB
#define TILES_PER_IMG 16   // HW/PIXB
#define ES_STRIDE 68       // padded row stride (floats) for codebook in smem
#define XS_STRIDE 68       // padded row stride (floats) for pixel tile in smem
#define TAU      2e-3f     // fp32 top-2 margin below which we refine in fp64

// device scratch (static allocation — allowed)
__device__ double       g_part[NBLK];
__device__ unsigned int g_done = 0;   // self-resetting via atomicInc wraparound

// packed dual-FP32 FMA: acc.{lo,hi} += a.{lo,hi} * b.{lo,hi}
__device__ __forceinline__ void ffma2(unsigned long long &acc,
                                      unsigned long long a,
                                      unsigned long long b) {
    asm("fma.rn.f32x2 %0, %1, %2, %0;" : "+l"(acc) : "l"(a), "l"(b));
}

__global__ __launch_bounds__(THREADS, 1)
void vq_main(const float* __restrict__ feat,
             const float* __restrict__ emb,
             float* __restrict__ out, int last) {
    extern __shared__ float sm[];
    float* es    = sm;                               // [512][68]
    float* xs    = es + KCODES * ES_STRIDE;          // [256][68]
    float* e2s   = xs + PIXB * XS_STRIDE;            // [512]
    int*   bestk = (int*)(e2s + KCODES);             // [256]
    float* wsum  = (float*)(bestk + PIXB);           // [16]
    int*   nflag = (int*)(wsum + 16);                // [1]
    int*   flags = nflag + 1;                        // [256]

    __shared__ int    s_last;
    __shared__ double s_red[THREADS];

    const int t   = threadIdx.x;
    const int bid = blockIdx.x;
    const int b   = bid >> 4;                         // 16 tiles per image
    const int p0  = (bid & (TILES_PER_IMG - 1)) * PIXB;
    const float* fbase = feat + ((size_t)b * DIM) * HW + p0;

    if (t == 0) *nflag = 0;

    // ---- stage codebook into smem (natural [k][d], padded rows, float4) ----
    {
        const float4* g4 = (const float4*)emb;
        for (int i = t; i < KCODES * (DIM / 4); i += THREADS) {
            int k  = i >> 4;
            int d4 = i & 15;
            *(float4*)&es[k * ES_STRIDE + d4 * 4] = g4[i];
        }
    }
    // ---- stage 256-pixel tile, transposing NCHW [d][p] -> xs[p][d] ----
    for (int i = t; i < PIXB * DIM; i += THREADS) {
        int d = i >> 8;
        int p = i & (PIXB - 1);
        xs[p * XS_STRIDE + d] = fbase[(size_t)d * HW + p];
    }
    __syncthreads();

    // ---- per-code squared norms ----
    for (int k = t; k < KCODES; k += THREADS) {
        const float* er = &es[k * ES_STRIDE];
        float s = 0.f;
        #pragma unroll
        for (int d = 0; d < DIM; d++) s = fmaf(er[d], er[d], s);
        e2s[k] = s;
    }
    __syncthreads();

    // ---- GEMM-style distance + top-2 argmin ----
    // thread tile: 4 pixels x 8 codes.
    //   pixels: pg + j*64   (j = 0..3)  -> x LDS conflict-free (row stride 1 in pg)
    //   codes:  kc*64 + jj*8 + kg       -> ev LDS conflict-free (row stride 1 in kg)
    const int pg = t >> 3;   // 0..63
    const int kg = t & 7;    // 0..7

    float s1[4], s2[4];
    int   i1[4];
    #pragma unroll
    for (int j = 0; j < 4; j++) { s1[j] = 3.4e38f; s2[j] = 3.4e38f; i1[j] = 0; }

    const float* xbase = &xs[pg * XS_STRIDE];

    for (int kc = 0; kc < 8; kc++) {
        const int kbase = kc * 64 + kg;
        const float* erow = &es[kbase * ES_STRIDE];

        unsigned long long acc[4][8];
        #pragma unroll
        for (int j = 0; j < 4; j++)
            #pragma unroll
            for (int jj = 0; jj < 8; jj++) acc[j][jj] = 0ULL;

        // unroll 1: keep live register set under the 128-reg cap (no spills)
        #pragma unroll 1
        for (int d4 = 0; d4 < 16; d4++) {
            ulonglong2 xv0 = *(const ulonglong2*)&xbase[0 * 64 * XS_STRIDE + d4 * 4];
            ulonglong2 xv1 = *(const ulonglong2*)&xbase[1 * 64 * XS_STRIDE + d4 * 4];
            ulonglong2 xv2 = *(const ulonglong2*)&xbase[2 * 64 * XS_STRIDE + d4 * 4];
            ulonglong2 xv3 = *(const ulonglong2*)&xbase[3 * 64 * XS_STRIDE + d4 * 4];
            #pragma unroll
            for (int jj = 0; jj < 8; jj++) {
                ulonglong2 ev =
                    *(const ulonglong2*)&erow[jj * 8 * ES_STRIDE + d4 * 4];
                // interleaved: 4 independent accs between reuses (no RAW stall)
                ffma2(acc[0][jj], xv0.x, ev.x);
                ffma2(acc[1][jj], xv1.x, ev.x);
                ffma2(acc[2][jj], xv2.x, ev.x);
                ffma2(acc[3][jj], xv3.x, ev.x);
                ffma2(acc[0][jj], xv0.y, ev.y);
                ffma2(acc[1][jj], xv1.y, ev.y);
                ffma2(acc[2][jj], xv2.y, ev.y);
                ffma2(acc[3][jj], xv3.y, ev.y);
            }
        }

        // epilogue: score = e2 - 2*dot ; top-2 (strict <, ascending code order)
        #pragma unroll
        for (int jj = 0; jj < 8; jj++) {
            const int code = kbase + jj * 8;
            const float e2v = e2s[code];
            #pragma unroll
            for (int j = 0; j < 4; j++) {
                unsigned long long a = acc[j][jj];
                float lo = __uint_as_float((unsigned)a);
                float hi = __uint_as_float((unsigned)(a >> 32));
                float dot = lo + hi;
                float score = fmaf(-2.f, dot, e2v);
                if (score < s1[j]) { s2[j] = s1[j]; s1[j] = score; i1[j] = code; }
                else if (score < s2[j]) { s2[j] = score; }
            }
        }
    }

    // ---- reduce top-2 across the 8 kg-lanes (same pg), tie -> smaller index ----
    #pragma unroll
    for (int j = 0; j < 4; j++) {
        float a1 = s1[j], a2 = s2[j];
        int   ai = i1[j];
        #pragma unroll
        for (int off = 1; off < 8; off <<= 1) {
            float o1 = __shfl_xor_sync(0xffffffffu, a1, off);
            int   oi = __shfl_xor_sync(0xffffffffu, ai, off);
            float o2 = __shfl_xor_sync(0xffffffffu, a2, off);
            if (o1 < a1 || (o1 == a1 && oi < ai)) {
                a2 = fminf(a1, o2); a1 = o1; ai = oi;
            } else {
                a2 = fminf(a2, o1);
            }
        }
        if (kg == 0) {
            const int p = j * 64 + pg;
            bestk[p] = ai;
            if (a2 - a1 < TAU) {
                int slot = atomicAdd(nflag, 1);
                flags[slot] = p;
            }
        }
    }
    __syncthreads();

    // ---- fp64 exact refinement of near-tie pixels (one warp per pixel) ----
    {
        const int nf   = *nflag;
        const int wid  = t >> 5;   // 16 warps
        const int lane = t & 31;
        for (int f = wid; f < nf; f += 16) {
            const int p = flags[f];
            const float* xr = &xs[p * XS_STRIDE];
            double bs = 1e300;
            int    bi = 0x7fffffff;
            for (int k = lane; k < KCODES; k += 32) {
                const float* er = &es[k * ES_STRIDE];
                double a0 = 0.0, a1d = 0.0, a2d = 0.0, a3d = 0.0;
                #pragma unroll
                for (int d = 0; d < DIM; d += 4) {
                    double d0 = (double)xr[d + 0] - (double)er[d + 0];
                    double d1 = (double)xr[d + 1] - (double)er[d + 1];
                    double d2 = (double)xr[d + 2] - (double)er[d + 2];
                    double d3 = (double)xr[d + 3] - (double)er[d + 3];
                    a0  = fma(d0, d0, a0);
                    a1d = fma(d1, d1, a1d);
                    a2d = fma(d2, d2, a2d);
                    a3d = fma(d3, d3, a3d);
                }
                double s = (a0 + a1d) + (a2d + a3d);
                if (s < bs) { bs = s; bi = k; }   // ascending k -> first occurrence
            }
            #pragma unroll
            for (int off = 16; off > 0; off >>= 1) {
                double os = __shfl_xor_sync(0xffffffffu, bs, off);
                int    oi = __shfl_xor_sync(0xffffffffu, bi, off);
                if (os < bs || (os == bs && oi < bi)) { bs = os; bi = oi; }
            }
            if (lane == 0) bestk[p] = bi;
        }
    }
    __syncthreads();

    // ---- gather output (NCHW) + elementwise-exact loss partial ----
    float lsum = 0.f;
    float* outb = out + ((size_t)b * DIM) * HW + p0;
    for (int i = t; i < PIXB * DIM; i += THREADS) {
        int d = i >> 8;
        int p = i & (PIXB - 1);
        int k = bestk[p];
        float ev = es[k * ES_STRIDE + d];
        float xv = xs[p * XS_STRIDE + d];
        outb[(size_t)d * HW + p] = ev;     // st == quant_out (forward value)
        float df = ev - xv;
        lsum = fmaf(df, df, lsum);
    }
    #pragma unroll
    for (int off = 16; off > 0; off >>= 1)
        lsum += __shfl_xor_sync(0xffffffffu, lsum, off);
    if ((t & 31) == 0) wsum[t >> 5] = lsum;
    __syncthreads();

    // ---- fused loss finalization: last block reduces all partials ----
    if (t == 0) {
        double s = 0.0;
        #pragma unroll
        for (int w = 0; w < 16; w++) s += (double)wsum[w];
        g_part[bid] = s;
        __threadfence();
        unsigned int old = atomicInc(&g_done, NBLK - 1);  // wraps to 0 => reset
        s_last = (old == NBLK - 1);
    }
    __syncthreads();

    if (s_last) {
        // deterministic fixed-order reduction of 512 partials
        s_red[t] = g_part[t];
        __syncthreads();
        #pragma unroll
        for (int sred = THREADS / 2; sred > 0; sred >>= 1) {
            if (t < sred) s_red[t] += s_red[t + sred];
            __syncthreads();
        }
        if (t == 0) {
            // loss = commitment + beta*codebook = 1.2 * mean(min dist^2)
            out[last] = (float)(1.2 * s_red[0]
                                / (double)(NBATCH * DIM * HW));
        }
    }
}

extern "C" void kernel_launch(void* const* d_in, const int* in_sizes, int n_in,
                              void* d_out, int out_size) {
    const float* feat = (const float*)d_in[0];   // (32, 64, 64, 64) fp32 NCHW
    const float* emb  = (const float*)d_in[1];   // (512, 64) fp32
    float* out = (float*)d_out;                  // st (8388608 floats) + loss (1)

    const int smem_bytes =
        (KCODES * ES_STRIDE + PIXB * XS_STRIDE + KCODES) * (int)sizeof(float)
        + PIXB * (int)sizeof(int)
        + 16 * (int)sizeof(float)
        + (1 + PIXB) * (int)sizeof(int);

    cudaFuncSetAttribute(vq_main, cudaFuncAttributeMaxDynamicSharedMemorySize,
                         smem_bytes);

    vq_main<<<NBLK, THREADS, smem_bytes>>>(feat, emb, out, out_size - 1);
}

// round 17
// speedup vs baseline: 1.3131x; 1.3117x over previous
#include <cuda_runtime.h>
#include <cuda_fp16.h>
#include <cstdint>

// Problem constants
#define KCODES   512
#define DIM      64
#define HW       4096      // 64*64
#define NBATCH   32
#define PIXB     128       // pixels per CTA (MMA M)
#define THREADS  256
#define NBLK     1024      // (NBATCH*HW)/PIXB
#define XS_STRIDE 67
#define TAU      2e-3f

// smem layout (bytes); MMA tiles on 1024B alignment
#define SM_AHI    0         // 128 rows x 128B (64 fp16)  = 16384
#define SM_ALO    16384     // 16384
#define SM_BHI    32768     // 512 rows x 128B            = 65536
#define SM_BLO    98304     // 65536
#define SM_XS     163840    // 128*67*4                   = 34304
#define SM_E2     198144    // 512*4
#define SM_BESTK  200192    // 128*4
#define SM_NFLAG  200704
#define SM_FLAGS  200708    // 128*4
#define SM_WSUM   201220    // 8*4
#define SM_TOTAL  201344

#define SWZ(o) ((o) ^ (((o) >> 3) & 0x70))

// device scratch (static — allowed)
__device__ unsigned int g_ehi_u[KCODES * DIM / 2];
__device__ unsigned int g_elo_u[KCODES * DIM / 2];
__device__ float        g_e2[KCODES];
__device__ double       g_part[NBLK];
__device__ unsigned int g_done = 0;

__device__ __forceinline__ uint32_t smem_u32(const void* p) {
    uint32_t a;
    asm("{ .reg .u64 t; cvta.to.shared.u64 t, %1; cvt.u32.u64 %0, t; }"
        : "=r"(a) : "l"(p));
    return a;
}
__device__ __forceinline__ void ldsm_x4(uint32_t* r, uint32_t addr) {
    asm volatile("ldmatrix.sync.aligned.m8n8.x4.shared.b16 {%0,%1,%2,%3}, [%4];"
                 : "=r"(r[0]), "=r"(r[1]), "=r"(r[2]), "=r"(r[3]) : "r"(addr));
}
__device__ __forceinline__ void ldsm_x2(uint32_t* r, uint32_t addr) {
    asm volatile("ldmatrix.sync.aligned.m8n8.x2.shared.b16 {%0,%1}, [%2];"
                 : "=r"(r[0]), "=r"(r[1]) : "r"(addr));
}
__device__ __forceinline__ void mma16816(float* c, const uint32_t* a,
                                         const uint32_t* b) {
    asm volatile(
        "mma.sync.aligned.m16n8k16.row.col.f32.f16.f16.f32 "
        "{%0,%1,%2,%3}, {%4,%5,%6,%7}, {%8,%9}, {%0,%1,%2,%3};"
        : "+f"(c[0]), "+f"(c[1]), "+f"(c[2]), "+f"(c[3])
        : "r"(a[0]), "r"(a[1]), "r"(a[2]), "r"(a[3]), "r"(b[0]), "r"(b[1]));
}

// ---------------- prep: split codebook to fp16 hi/lo + e2 ----------------
__global__ void vq_prep(const float* __restrict__ emb) {
    int i = blockIdx.x * blockDim.x + threadIdx.x;   // 0..16383
    if (i < KCODES * DIM / 2) {
        float v0 = emb[2 * i], v1 = emb[2 * i + 1];
        __half h0 = __float2half_rn(v0), h1 = __float2half_rn(v1);
        __half l0 = __float2half_rn(v0 - __half2float(h0));
        __half l1 = __float2half_rn(v1 - __half2float(h1));
        __half2 H = __halves2half2(h0, h1), L = __halves2half2(l0, l1);
        g_ehi_u[i] = *(uint32_t*)&H;
        g_elo_u[i] = *(uint32_t*)&L;
    }
    if (i < KCODES) {
        const float* er = &emb[i * DIM];
        float s = 0.f;
        #pragma unroll
        for (int d = 0; d < DIM; d++) s = fmaf(er[d], er[d], s);
        g_e2[i] = s;
    }
}

// ---------------- main ----------------
__global__ __launch_bounds__(THREADS, 1)
void vq_main(const float* __restrict__ feat,
             const float* __restrict__ emb,
             float* __restrict__ out, int last) {
    extern __shared__ char sm[];
    const uint32_t smb = smem_u32(sm);
    float* xs    = (float*)(sm + SM_XS);
    float* e2s   = (float*)(sm + SM_E2);
    int*   bestk = (int*)(sm + SM_BESTK);
    int*   nflag = (int*)(sm + SM_NFLAG);
    int*   flags = (int*)(sm + SM_FLAGS);
    float* wsum  = (float*)(sm + SM_WSUM);

    __shared__ int    s_last;
    __shared__ double s_red[THREADS];

    const int t    = threadIdx.x;
    const int wid  = t >> 5;
    const int lane = t & 31;
    const int bid  = blockIdx.x;
    const int b    = bid >> 5;                 // 32 tiles per image
    const int p0   = (bid & 31) * PIXB;
    const float* fbase = feat + ((size_t)b * DIM) * HW + p0;

    if (t == 0) *nflag = 0;

    // ---- stage X fp32 (transpose NCHW [d][p] -> xs[p][d]) ----
    for (int i = t; i < PIXB * DIM; i += THREADS) {
        int d = i >> 7, p = i & 127;
        xs[p * XS_STRIDE + d] = fbase[(size_t)d * HW + p];
    }
    // ---- stage B halves (pre-split fp16) into swizzled 128B rows ----
    for (int i = t; i < KCODES * DIM / 2; i += THREADS) {
        int k = i >> 5, dp = i & 31;
        uint32_t off = SWZ(k * 128 + dp * 4);
        *(uint32_t*)(sm + SM_BHI + off) = g_ehi_u[i];
        *(uint32_t*)(sm + SM_BLO + off) = g_elo_u[i];
    }
    for (int k = t; k < KCODES; k += THREADS) e2s[k] = g_e2[k];
    __syncthreads();

    // ---- convert X -> A halves: fp16 split of (-2*x), swizzled rows ----
    for (int i = t; i < PIXB * DIM / 2; i += THREADS) {
        int p = i >> 5, dp = i & 31;
        float v0 = -2.f * xs[p * XS_STRIDE + dp * 2];
        float v1 = -2.f * xs[p * XS_STRIDE + dp * 2 + 1];
        __half h0 = __float2half_rn(v0), h1 = __float2half_rn(v1);
        __half l0 = __float2half_rn(v0 - __half2float(h0));
        __half l1 = __float2half_rn(v1 - __half2float(h1));
        uint32_t off = SWZ(p * 128 + dp * 4);
        __half2 H = __halves2half2(h0, h1), L = __halves2half2(l0, l1);
        *(uint32_t*)(sm + SM_AHI + off) = *(uint32_t*)&H;
        *(uint32_t*)(sm + SM_ALO + off) = *(uint32_t*)&L;
    }
    __syncthreads();

    // ---- HMMA GEMM: warp owns 16 pixels x all 512 codes ----
    // score(p,k) = e2[k] - 2*x.e  accumulated via 3-term fp16 split
    const int wbase = wid * 16;
    // A ldmatrix address: row = wbase + (lane&15), 16B chunk = lane>>4
    const uint32_t a_row  = (uint32_t)(wbase + (lane & 15)) * 128
                          + (uint32_t)(lane >> 4) * 16;
    // B ldmatrix address (x2, lanes 0-15): code row = cb + (lane&7),
    // 16B chunk = (lane>>3)&1
    const uint32_t b_lanerow = (uint32_t)(lane & 7) * 128
                             + (uint32_t)((lane >> 3) & 1) * 16;

    float s1a = 3.4e38f, s2a = 3.4e38f;  int i1a = 0;   // row g = lane>>2
    float s1b = 3.4e38f, s2b = 3.4e38f;  int i1b = 0;   // row g+8

    for (int nc = 0; nc < 4; nc++) {
        float acc[16][4];
        #pragma unroll
        for (int nt = 0; nt < 16; nt++)
            #pragma unroll
            for (int j = 0; j < 4; j++) acc[nt][j] = 0.f;

        #pragma unroll
        for (int ks = 0; ks < 4; ks++) {
            uint32_t ahi[4], alo[4];
            ldsm_x4(ahi, smb + SM_AHI + SWZ(a_row + ks * 32));
            ldsm_x4(alo, smb + SM_ALO + SWZ(a_row + ks * 32));
            #pragma unroll
            for (int nt = 0; nt < 16; nt++) {
                const uint32_t brow = (uint32_t)(nc * 128 + nt * 8) * 128
                                    + b_lanerow + ks * 32;
                uint32_t bhi[2], blo[2];
                ldsm_x2(bhi, smb + SM_BHI + SWZ(brow));
                ldsm_x2(blo, smb + SM_BLO + SWZ(brow));
                mma16816(acc[nt], ahi, bhi);
                mma16816(acc[nt], ahi, blo);
                mma16816(acc[nt], alo, bhi);
            }
        }

        // scores + top-2 (codes ascending within thread -> first-occurrence)
        #pragma unroll
        for (int nt = 0; nt < 16; nt++) {
            const int cbase = nc * 128 + nt * 8 + (lane & 3) * 2;
            #pragma unroll
            for (int j = 0; j < 2; j++) {
                const int code = cbase + j;
                const float e2v = e2s[code];
                float sc0 = e2v + acc[nt][j];       // row g
                float sc1 = e2v + acc[nt][j + 2];   // row g+8
                if (sc0 < s1a) { s2a = s1a; s1a = sc0; i1a = code; }
                else if (sc0 < s2a) { s2a = sc0; }
                if (sc1 < s1b) { s2b = s1b; s1b = sc1; i1b = code; }
                else if (sc1 < s2b) { s2b = sc1; }
            }
        }
    }

    // ---- combine top-2 across the quad (lanes differing in bits 0-1) ----
    #pragma unroll
    for (int off = 1; off < 4; off <<= 1) {
        float o1 = __shfl_xor_sync(0xffffffffu, s1a, off);
        int   oi = __shfl_xor_sync(0xffffffffu, i1a, off);
        float o2 = __shfl_xor_sync(0xffffffffu, s2a, off);
        if (o1 < s1a || (o1 == s1a && oi < i1a)) {
            s2a = fminf(s1a, o2); s1a = o1; i1a = oi;
        } else s2a = fminf(s2a, o1);

        o1 = __shfl_xor_sync(0xffffffffu, s1b, off);
        oi = __shfl_xor_sync(0xffffffffu, i1b, off);
        o2 = __shfl_xor_sync(0xffffffffu, s2b, off);
        if (o1 < s1b || (o1 == s1b && oi < i1b)) {
            s2b = fminf(s1b, o2); s1b = o1; i1b = oi;
        } else s2b = fminf(s2b, o1);
    }
    if ((lane & 3) == 0) {
        const int g  = lane >> 2;
        const int pA = wbase + g;
        const int pB = wbase + g + 8;
        bestk[pA] = i1a;
        bestk[pB] = i1b;
        if (s2a - s1a < TAU) flags[atomicAdd(nflag, 1)] = pA;
        if (s2b - s1b < TAU) flags[atomicAdd(nflag, 1)] = pB;
    }
    __syncthreads();

    // ---- fp64 exact refinement of near-tie pixels (one warp per pixel) ----
    {
        const int nf = *nflag;
        for (int f = wid; f < nf; f += 8) {
            const int p = flags[f];
            const float* xr = &xs[p * XS_STRIDE];
            double bs = 1e300;
            int    bi = 0x7fffffff;
            for (int k = lane; k < KCODES; k += 32) {
                const float* er = &emb[k * DIM];
                double a0 = 0.0, a1 = 0.0, a2 = 0.0, a3 = 0.0;
                #pragma unroll
                for (int d = 0; d < DIM; d += 4) {
                    double d0 = (double)xr[d + 0] - (double)er[d + 0];
                    double d1 = (double)xr[d + 1] - (double)er[d + 1];
                    double d2 = (double)xr[d + 2] - (double)er[d + 2];
                    double d3 = (double)xr[d + 3] - (double)er[d + 3];
                    a0 = fma(d0, d0, a0);
                    a1 = fma(d1, d1, a1);
                    a2 = fma(d2, d2, a2);
                    a3 = fma(d3, d3, a3);
                }
                double s = (a0 + a1) + (a2 + a3);
                if (s < bs) { bs = s; bi = k; }
            }
            #pragma unroll
            for (int off = 16; off > 0; off >>= 1) {
                double os = __shfl_xor_sync(0xffffffffu, bs, off);
                int    oi = __shfl_xor_sync(0xffffffffu, bi, off);
                if (os < bs || (os == bs && oi < bi)) { bs = os; bi = oi; }
            }
            if (lane == 0) bestk[p] = bi;
        }
    }
    __syncthreads();

    // ---- gather output (NCHW, exact fp32 codebook) + loss partial ----
    float lsum = 0.f;
    float* outb = out + ((size_t)b * DIM) * HW + p0;
    for (int i = t; i < PIXB * DIM; i += THREADS) {
        int d = i >> 7, p = i & 127;
        int k = bestk[p];
        float ev = emb[k * DIM + d];
        float xv = xs[p * XS_STRIDE + d];
        outb[(size_t)d * HW + p] = ev;
        float df = ev - xv;
        lsum = fmaf(df, df, lsum);
    }
    #pragma unroll
    for (int off = 16; off > 0; off >>= 1)
        lsum += __shfl_xor_sync(0xffffffffu, lsum, off);
    if (lane == 0) wsum[wid] = lsum;
    __syncthreads();

    // ---- fused loss finalization: last block reduces all partials ----
    if (t == 0) {
        double s = 0.0;
        #pragma unroll
        for (int w = 0; w < 8; w++) s += (double)wsum[w];
        g_part[bid] = s;
        __threadfence();
        unsigned int old = atomicInc(&g_done, NBLK - 1);  // wraps to 0 => reset
        s_last = (old == NBLK - 1);
    }
    __syncthreads();

    if (s_last) {
        double v = g_part[t * 4 + 0] + g_part[t * 4 + 1]
                 + g_part[t * 4 + 2] + g_part[t * 4 + 3];
        s_red[t] = v;
        __syncthreads();
        #pragma unroll
        for (int sred = THREADS / 2; sred > 0; sred >>= 1) {
            if (t < sred) s_red[t] += s_red[t + sred];
            __syncthreads();
        }
        if (t == 0) {
            // loss = commitment + beta*codebook = 1.2 * mean(min dist^2)
            out[last] = (float)(1.2 * s_red[0] / (double)(NBATCH * DIM * HW));
        }
    }
}

extern "C" void kernel_launch(void* const* d_in, const int* in_sizes, int n_in,
                              void* d_out, int out_size) {
    const float* feat = (const float*)d_in[0];   // (32, 64, 64, 64) fp32 NCHW
    const float* emb  = (const float*)d_in[1];   // (512, 64) fp32
    float* out = (float*)d_out;                  // st (8388608 floats) + loss (1)

    cudaFuncSetAttribute(vq_main, cudaFuncAttributeMaxDynamicSharedMemorySize,
                         SM_TOTAL);

    vq_prep<<<64, 256>>>(emb);
    vq_main<<<NBLK, THREADS, SM_TOTAL>>>(feat, emb, out, out_size - 1);
}